// round 8
// baseline (speedup 1.0000x reference)
#include <cuda_runtime.h>
#include <math.h>

#define N     1024
#define NN    (N*N)
#define NB    32
#define NSTEP 32
#define BATCH 16

// ---------------- device scratch (no allocations allowed) ----------------
__device__ float g_lu[(size_t)BATCH * NN];     // 64 MB destructible LU workspace
__device__ float g_comb[(size_t)3 * NN];       // combined right-hand matrices C0,C1,C2
__device__ float g_logdet[BATCH];
__device__ float g_swaptmp[(size_t)BATCH * 64 * N];  // row-gather staging (4 MB)

struct Hdr {
    int   active;
    int   idx[8];
    float weff[10];
    float beff;
};
__device__ Hdr g_hdr;

// ---------------- stage A: copy x -> LU workspace, zero logdets ----------------
__global__ void copy_kernel(const float* __restrict__ x) {
    size_t i = (size_t)blockIdx.x * blockDim.x + threadIdx.x;
    const float4* src = (const float4*)x;
    float4* dst = (float4*)g_lu;
    if (i < (size_t)BATCH * NN / 4) dst[i] = src[i];
    if (i < BATCH) g_logdet[i] = 0.0f;
}

// shifted-row elimination: c[t-1] = c[t] - lv * s_piv[t], deposit lv at slot 31.
// Reads s_piv via float4 (8 x LDS.128 instead of 31 scalar LDS).
#define ELIM_ROW(c, lv)                                           \
    do {                                                          \
        _Pragma("unroll")                                         \
        for (int q = 0; q < 8; q++) {                             \
            float4 pq = *(const float4*)&s_piv[4 * q];            \
            float pe0 = pq.x, pe1 = pq.y, pe2 = pq.z, pe3 = pq.w; \
            if (q > 0) (c)[4*q - 1] = (c)[4*q]     - (lv) * pe0;  \
            (c)[4*q + 0] = (c)[4*q + 1] - (lv) * pe1;             \
            (c)[4*q + 1] = (c)[4*q + 2] - (lv) * pe2;             \
            if (q < 7) (c)[4*q + 2] = (c)[4*q + 3] - (lv) * pe3;  \
            else       (c)[NB - 2]   = (c)[NB - 1] - (lv) * pe3;  \
        }                                                         \
        (c)[NB - 1] = (lv);                                       \
    } while (0)

// ---------------- stage B1: panel factorization, relabeling shift-array scheme ----
// One CTA per matrix, 512 threads, 2 register rows/thread. Register rows never
// move; logical-position tags track pivot swaps. Per step: 64-bit-key warp
// reduce + vectorized redundant scan, parallel owner-exit de-rotation (3 syncs,
// no serial segment), float4-vectorized shifted elimination. B-row path is
// branched out entirely once R <= 512. Arithmetic identical to prior round.
__global__ void __launch_bounds__(512) lu_panel(int k) {
    int m = blockIdx.x;
    float* A = g_lu + (size_t)m * NN;
    float* tmp = g_swaptmp + (size_t)m * 64 * N;
    int kb = k * NB;
    int R  = N - kb;
    int W  = N - kb - NB;
    int tid = threadIdx.x;
    int lane = tid & 31, wrp = tid >> 5;
    bool useB = (R > 512);

    __shared__ __align__(16) unsigned long long rvi[16];
    __shared__ __align__(16) float s_raw[NB];   // owner's raw shifted row
    __shared__ __align__(16) float s_piv[NB];   // de-rot staged + zero-padded
    __shared__ float s_U[NB][NB + 1];           // de-rotated exited rows (diag L|U)
    __shared__ float s_abs[NB];                 // |pivot| per step
    __shared__ int   s_src[N];
    __shared__ int   s_aff[64];
    __shared__ int   s_na;

    int relA = tid, relB = tid + 512;
    bool actA = relA < R;
    bool actB = useB && (relB < R);
    int myA = relA, myB = relB;
    int exA = -1, exB = -1;

    float ca[NB], cb[NB];
    {
        const float4* pa = (const float4*)(A + (size_t)(kb + relA) * N + kb);
        #pragma unroll
        for (int q = 0; q < 8; q++) {
            float4 v = actA ? pa[q] : make_float4(0.f, 0.f, 0.f, 0.f);
            ca[4*q+0] = v.x; ca[4*q+1] = v.y; ca[4*q+2] = v.z; ca[4*q+3] = v.w;
        }
        if (useB) {
            const float4* pb = (const float4*)(A + (size_t)(kb + relB) * N + kb);
            #pragma unroll
            for (int q = 0; q < 8; q++) {
                float4 w = actB ? pb[q] : make_float4(0.f, 0.f, 0.f, 0.f);
                cb[4*q+0] = w.x; cb[4*q+1] = w.y; cb[4*q+2] = w.z; cb[4*q+3] = w.w;
            }
        }
    }
    if (tid == 0) s_na = 0;

    #pragma unroll 1
    for (int j = 0; j < NB; j++) {
        // ---- candidate key: (|value| bits << 32) | (~logical index) ----
        unsigned long long key = 0ull;
        if (actA)
            key = ((unsigned long long)__float_as_uint(fabsf(ca[0])) << 32)
                | (unsigned long long)(0xFFFFFFFFu - (unsigned)myA);
        if (useB && actB) {
            unsigned long long k2 =
                  ((unsigned long long)__float_as_uint(fabsf(cb[0])) << 32)
                | (unsigned long long)(0xFFFFFFFFu - (unsigned)myB);
            if (k2 > key) key = k2;
        }
        #pragma unroll
        for (int o = 16; o > 0; o >>= 1) {
            unsigned long long ok = __shfl_down_sync(0xffffffffu, key, o);
            if (ok > key) key = ok;
        }
        if (lane == 0) rvi[wrp] = key;
        __syncthreads();

        // ---- vectorized redundant scan: every thread learns the pivot ----
        unsigned long long bk;
        {
            const ulonglong2* rv2 = (const ulonglong2*)rvi;
            ulonglong2 v0 = rv2[0];
            bk = (v0.x > v0.y) ? v0.x : v0.y;
            #pragma unroll
            for (int w = 1; w < 8; w++) {
                ulonglong2 v = rv2[w];
                if (v.x > bk) bk = v.x;
                if (v.y > bk) bk = v.y;
            }
        }
        int p = (int)(0xFFFFFFFFu - (unsigned)(bk & 0xFFFFFFFFull));
        if (tid == 0) s_abs[j] = __uint_as_float((unsigned)(bk >> 32));

        // ---- owner exits (vectorized raw dump); slot j relabels to p ----
        if (actA) {
            if (myA == p) {
                float4* rw = (float4*)s_raw;
                #pragma unroll
                for (int q = 0; q < 8; q++)
                    rw[q] = make_float4(ca[4*q+0], ca[4*q+1], ca[4*q+2], ca[4*q+3]);
                actA = false; exA = j;
            } else if (myA == j) myA = p;
        }
        if (useB && actB) {
            if (myB == p) {
                float4* rw = (float4*)s_raw;
                #pragma unroll
                for (int q = 0; q < 8; q++)
                    rw[q] = make_float4(cb[4*q+0], cb[4*q+1], cb[4*q+2], cb[4*q+3]);
                actB = false; exB = j;
            } else if (myB == j) myB = p;
        }
        __syncthreads();

        // ---- parallel de-rotation + zero-padded pivot staging ----
        if (tid < NB) {
            float v = s_raw[tid];
            int col = (tid <= NB - 1 - j) ? (j + tid) : (tid - (NB - j));
            s_U[j][col] = v;
            s_piv[tid] = (tid <= NB - 1 - j) ? v : 0.0f;
        }
        __syncthreads();

        // ---- shifted elimination + L deposit (float4 piv reads) ----
        float inv = 1.0f / s_piv[0];
        if (actA) {
            float lv = ca[0] * inv;
            ELIM_ROW(ca, lv);
        }
        if (useB) {
            if (actB) {
                float lv = cb[0] * inv;
                ELIM_ROW(cb, lv);
            }
        }
    }
    __syncthreads();

    // ---- diag block writeback (L|U of the 32 exited rows) ----
    for (int i = tid; i < NB * NB; i += 512)
        A[(size_t)(kb + i / NB) * N + kb + (i % NB)] = s_U[i / NB][i % NB];

    // ---- L21 writeback: surviving rows land at their final logical slot ----
    if (actA) {
        float4* pw = (float4*)(A + (size_t)(kb + myA) * N + kb);
        #pragma unroll
        for (int q = 0; q < 8; q++)
            pw[q] = make_float4(ca[4*q+0], ca[4*q+1], ca[4*q+2], ca[4*q+3]);
    }
    if (useB && actB) {
        float4* pw = (float4*)(A + (size_t)(kb + myB) * N + kb);
        #pragma unroll
        for (int q = 0; q < 8; q++)
            pw[q] = make_float4(cb[4*q+0], cb[4*q+1], cb[4*q+2], cb[4*q+3]);
    }

    // ---- logdet: 32 parallel logs + warp-reduce sum ----
    if (tid < 32) {
        float lg = logf(fmaxf(s_abs[tid], 1e-45f));
        #pragma unroll
        for (int o = 16; o > 0; o >>= 1) lg += __shfl_down_sync(0xffffffffu, lg, o);
        if (tid == 0) g_logdet[m] += lg;
    }

    // ---- build source map: final content of slot r = original row src[r] ----
    if (relA < R) {
        if (exA >= 0) s_src[exA] = relA; else s_src[myA] = relA;
    }
    if (useB && relB < R) {
        if (exB >= 0) s_src[exB] = relB; else s_src[myB] = relB;
    }
    __syncthreads();
    for (int r = tid; r < R; r += 512) {
        if (s_src[r] != r) {
            int i = atomicAdd(&s_na, 1);
            s_aff[i] = r;
        }
    }
    __syncthreads();
    int na = s_na;
    if (W <= 0 || na == 0) return;

    // ---- permutation gather on trailing columns: two coalesced passes ----
    int W4 = W >> 2;
    for (int idx = tid; idx < na * W4; idx += 512) {
        int i = idx / W4, c = idx % W4;
        int sr = s_src[s_aff[i]];
        *(float4*)(tmp + (size_t)i * W + 4 * c) =
            *(const float4*)(A + (size_t)(kb + sr) * N + kb + NB + 4 * c);
    }
    __syncthreads();
    for (int idx = tid; idx < na * W4; idx += 512) {
        int i = idx / W4, c = idx % W4;
        int dr = s_aff[i];
        *(float4*)(A + (size_t)(kb + dr) * N + kb + NB + 4 * c) =
            *(const float4*)(tmp + (size_t)i * W + 4 * c);
    }
}

// ---------------- stage B2: fused local-TRSM + trailing update (128x128, 8x8) ----
__global__ void __launch_bounds__(256) lu_update(int k) {
    int kb  = k * NB;
    int off = kb + NB;
    int W   = N - off;
    int m   = blockIdx.z;
    float* A = g_lu + (size_t)m * NN;
    int r0 = blockIdx.y * 128, c0 = blockIdx.x * 128;
    int tid = threadIdx.x;

    __shared__ float D[NB][NB + 1];     // factored diag block (L unit-lower + U)
    __shared__ float sL[128][NB + 1];   // L21 strip (this CTA's rows)
    __shared__ float sU[NB][132];       // U12 strip (this CTA's 128 cols)

    for (int i = tid; i < NB * NB; i += 256) {
        int r = i / NB, c = i % NB;
        D[r][c] = A[(size_t)(kb + r) * N + kb + c];
    }
    for (int i = tid; i < 128 * NB; i += 256) {
        int r = i / NB, j = i % NB;
        sL[r][j] = (r0 + r < W) ? A[(size_t)(off + r0 + r) * N + kb + j] : 0.0f;
    }
    for (int i = tid; i < NB * 128; i += 256) {
        int r = i / 128, c = i % 128;
        int col = c0 + c;
        sU[r][c] = (col < W) ? A[(size_t)(kb + r) * N + off + col] : 0.0f;
    }
    __syncthreads();

    // local TRSM: threads 0..127 each solve one U12 column (L11 unit-lower)
    if (tid < 128) {
        float v[NB];
        #pragma unroll
        for (int i = 0; i < NB; i++) v[i] = sU[i][tid];
        #pragma unroll 1
        for (int j = 0; j < NB; j++) {
            float vj = v[j];
            #pragma unroll
            for (int i = 0; i < NB; i++)
                if (i > j) v[i] -= D[i][j] * vj;
        }
        #pragma unroll
        for (int i = 0; i < NB; i++) sU[i][tid] = v[i];
    }
    __syncthreads();

    // trailing update: 128x128 tile, 8x8 per thread (two 64-col halves)
    int tx = tid & 15, ty = tid >> 4;
    float acc[8][8] = {};
    #pragma unroll
    for (int j = 0; j < NB; j++) {
        float4 b0 = *(const float4*)&sU[j][tx * 4];
        float4 b1 = *(const float4*)&sU[j][64 + tx * 4];
        float b[8] = {b0.x, b0.y, b0.z, b0.w, b1.x, b1.y, b1.z, b1.w};
        float a[8];
        #pragma unroll
        for (int i = 0; i < 8; i++) a[i] = sL[ty * 8 + i][j];
        #pragma unroll
        for (int i = 0; i < 8; i++)
            #pragma unroll
            for (int l = 0; l < 8; l++) acc[i][l] += a[i] * b[l];
    }
    #pragma unroll
    for (int i = 0; i < 8; i++) {
        int row = r0 + ty * 8 + i;
        if (row >= W) continue;
        float* orow = A + (size_t)(off + row) * N + off;
        #pragma unroll
        for (int l = 0; l < 8; l++) {
            int col = c0 + ((l < 4) ? (tx * 4 + l) : (64 + tx * 4 + l - 4));
            if (col < W) orow[col] -= acc[i][l];
        }
    }
}

// ---------------- stage C: scores, top-k, fused weights, bool output ----------------
__global__ void head_kernel(const unsigned char* __restrict__ flags,
                            const float* __restrict__ w1, const float* __restrict__ b1,
                            const float* __restrict__ w2, const float* __restrict__ b2,
                            float* __restrict__ out, int out_size) {
    if (blockIdx.x != 0 || threadIdx.x != 0) return;

    int f[16];
    bool any_off4 = false;
    for (int i = 0; i < 16; i++)
        if ((i & 3) && flags[i]) any_off4 = true;
    if (any_off4) {
        for (int i = 0; i < 16; i++) f[i] = flags[i] ? 1 : 0;
    } else {
        const int* fi = (const int*)flags;
        for (int i = 0; i < 16; i++) f[i] = fi[i] ? 1 : 0;
    }

    int sum = 0;
    for (int i = 0; i < 16; i++) sum += f[i];
    int active = (sum >= 4) ? 1 : 0;

    float neg_inf = __int_as_float(0xff800000);
    float sc[16];
    for (int i = 0; i < 16; i++) sc[i] = f[i] ? g_logdet[i] : neg_inf;

    int used[16] = {};
    for (int t = 0; t < 8; t++) {
        int best = -1;
        float bv = neg_inf;
        for (int i = 0; i < 16; i++) {
            if (used[i]) continue;
            if (best < 0 || sc[i] > bv) { best = i; bv = sc[i]; }
        }
        used[best] = 1;
        g_hdr.idx[t] = best;
    }

    for (int c = 0; c < 10; c++) {
        float a = 0.0f;
        for (int h = 0; h < 32; h++) a += w2[h] * w1[h * 10 + c];
        g_hdr.weff[c] = a;
    }
    float be = b2[0];
    for (int h = 0; h < 32; h++) be += w2[h] * b1[h];
    g_hdr.beff = be;
    g_hdr.active = active;

    for (int i = NN; i < out_size; i++) out[i] = active ? 1.0f : 0.0f;
}

// ---------------- stage D1: combined right matrices ----------------
__global__ void combine_kernel(const float* __restrict__ x) {
    int i = blockIdx.x * blockDim.x + threadIdx.x;
    if (i >= NN / 4) return;
    const float4* T1 = (const float4*)(x + (size_t)g_hdr.idx[1] * NN);
    const float4* T2 = (const float4*)(x + (size_t)g_hdr.idx[2] * NN);
    const float4* T3 = (const float4*)(x + (size_t)g_hdr.idx[3] * NN);
    float w0 = g_hdr.weff[0], w1 = g_hdr.weff[1], w2 = g_hdr.weff[2];
    float w3 = g_hdr.weff[3], w4 = g_hdr.weff[4], w5 = g_hdr.weff[5];
    float4 a = T1[i], b = T2[i], c = T3[i];
    float4 r0, r1, r2;
    r0.x = w0*a.x + w1*b.x + w2*c.x;  r0.y = w0*a.y + w1*b.y + w2*c.y;
    r0.z = w0*a.z + w1*b.z + w2*c.z;  r0.w = w0*a.w + w1*b.w + w2*c.w;
    r1.x = w3*b.x + w4*c.x;  r1.y = w3*b.y + w4*c.y;
    r1.z = w3*b.z + w4*c.z;  r1.w = w3*b.w + w4*c.w;
    r2.x = w5*c.x;  r2.y = w5*c.y;  r2.z = w5*c.z;  r2.w = w5*c.w;
    ((float4*)g_comb)[i]            = r0;
    ((float4*)(g_comb + NN))[i]     = r1;
    ((float4*)(g_comb + 2*NN))[i]   = r2;
}

// ---------------- stage D2: fused 3-GEMM + preserve channels + bias ----------------
#define SA(p,r,j) sA[((p) * 128 + (r)) * 33 + (j)]
#define SB(p,j,c) sB[((p) * NB + (j)) * 68 + (c)]
__global__ void __launch_bounds__(256) final_kernel(const float* __restrict__ x,
                                                    float* __restrict__ out, int out_size) {
    extern __shared__ float sm[];
    float* sA = sm;                         // 3 * 128 * 33
    float* sB = sm + 3 * 128 * 33;          // 3 * NB * 68

    int r0 = blockIdx.y * 128, c0 = blockIdx.x * 64;
    int tid = threadIdx.x, tx = tid & 15, ty = tid >> 4;

    if (!g_hdr.active) {
        #pragma unroll
        for (int i = 0; i < 8; i++) {
            int row = r0 + ty * 8 + i;
            #pragma unroll
            for (int l = 0; l < 4; l++) {
                int p = row * N + c0 + tx * 4 + l;
                if (p < out_size) out[p] = 0.0f;
            }
        }
        return;
    }

    const float* L[3] = { x + (size_t)g_hdr.idx[0] * NN,
                          x + (size_t)g_hdr.idx[1] * NN,
                          x + (size_t)g_hdr.idx[2] * NN };
    const float* C[3] = { g_comb, g_comb + NN, g_comb + 2 * NN };

    float acc[8][4] = {};
    for (int kc = 0; kc < N; kc += NB) {
        #pragma unroll
        for (int p = 0; p < 3; p++) {
            for (int i = tid; i < 128 * NB; i += 256) {
                int r = i / NB, j = i % NB;
                SA(p, r, j) = L[p][(size_t)(r0 + r) * N + kc + j];
            }
            for (int i = tid; i < NB * 64; i += 256) {
                int j = i / 64, c = i % 64;
                SB(p, j, c) = C[p][(size_t)(kc + j) * N + c0 + c];
            }
        }
        __syncthreads();
        #pragma unroll 4
        for (int jj = 0; jj < NB; jj++) {
            #pragma unroll
            for (int p = 0; p < 3; p++) {
                float4 bv = *(const float4*)&SB(p, jj, tx * 4);
                float b[4] = {bv.x, bv.y, bv.z, bv.w};
                float a[8];
                #pragma unroll
                for (int i = 0; i < 8; i++) a[i] = SA(p, ty * 8 + i, jj);
                #pragma unroll
                for (int i = 0; i < 8; i++)
                    #pragma unroll
                    for (int l = 0; l < 4; l++) acc[i][l] += a[i] * b[l];
            }
        }
        __syncthreads();
    }

    const float* P0 = x + (size_t)g_hdr.idx[4] * NN;
    const float* P1 = x + (size_t)g_hdr.idx[5] * NN;
    const float* P2 = x + (size_t)g_hdr.idx[6] * NN;
    const float* P3 = x + (size_t)g_hdr.idx[7] * NN;
    float w6 = g_hdr.weff[6], w7 = g_hdr.weff[7], w8 = g_hdr.weff[8], w9 = g_hdr.weff[9];
    float be = g_hdr.beff;

    #pragma unroll
    for (int i = 0; i < 8; i++) {
        int row = r0 + ty * 8 + i;
        #pragma unroll
        for (int l = 0; l < 4; l++) {
            int col = c0 + tx * 4 + l;
            int p = row * N + col;
            float v = acc[i][l] + w6 * P0[p] + w7 * P1[p] + w8 * P2[p] + w9 * P3[p] + be;
            if (p < out_size) out[p] = v;
        }
    }
}

// ---------------- host launcher ----------------
extern "C" void kernel_launch(void* const* d_in, const int* in_sizes, int n_in,
                              void* d_out, int out_size) {
    const float*         x     = (const float*)d_in[0];
    const unsigned char* flags = (const unsigned char*)d_in[1];
    const float*         w1    = (const float*)d_in[2];
    const float*         b1    = (const float*)d_in[3];
    const float*         w2    = (const float*)d_in[4];
    const float*         b2    = (const float*)d_in[5];
    float*               out   = (float*)d_out;

    int fin_smem = (3 * 128 * 33 + 3 * NB * 68) * (int)sizeof(float);
    cudaFuncSetAttribute(final_kernel, cudaFuncAttributeMaxDynamicSharedMemorySize, fin_smem);

    copy_kernel<<<(BATCH * NN / 4 + 255) / 256, 256>>>(x);

    for (int k = 0; k < NSTEP; k++) {
        int W = N - (k + 1) * NB;
        lu_panel<<<BATCH, 512>>>(k);
        if (W > 0) {
            dim3 g((W + 127) / 128, (W + 127) / 128, BATCH);
            lu_update<<<g, 256>>>(k);
        }
    }

    head_kernel<<<1, 1>>>(flags, w1, b1, w2, b2, out, out_size);
    combine_kernel<<<(NN / 4 + 255) / 256, 256>>>(x);
    final_kernel<<<dim3(16, 8), 256, fin_smem>>>(x, out, out_size);
}

// round 11
// speedup vs baseline: 1.7237x; 1.7237x over previous
#include <cuda_runtime.h>
#include <math.h>

#define N     1024
#define NN    (N*N)
#define NB    32
#define NSTEP 32
#define BATCH 16

// ---------------- device scratch (no allocations allowed) ----------------
__device__ float g_lu[(size_t)BATCH * NN];     // 64 MB destructible LU workspace
__device__ float g_comb[(size_t)3 * NN];       // combined right-hand matrices C0,C1,C2
__device__ float g_logdet[BATCH];
__device__ float g_swaptmp[(size_t)BATCH * 64 * N];  // row-gather staging (4 MB)
__device__ int   g_na[BATCH];                  // # affected rows per matrix
__device__ int   g_aff[BATCH * 64];            // affected destination rows (rel)
__device__ int   g_srcof[BATCH * 64];          // their source rows (rel)

struct Hdr {
    int   active;
    int   idx[8];
    float weff[10];
    float beff;
};
__device__ Hdr g_hdr;

// ---------------- stage A: copy x -> LU workspace, zero logdets ----------------
__global__ void copy_kernel(const float* __restrict__ x) {
    size_t i = (size_t)blockIdx.x * blockDim.x + threadIdx.x;
    const float4* src = (const float4*)x;
    float4* dst = (float4*)g_lu;
    if (i < (size_t)BATCH * NN / 4) dst[i] = src[i];
    if (i < BATCH) g_logdet[i] = 0.0f;
}

// ---------------- fused kernel: panel(kp) CTAs + rest-update(kr) CTAs --------
// Shared-memory union: panel role and rest role use disjoint layouts.
union SmemU {
    struct {
        unsigned long long rvi[16];
        float s_piv[NB];
        float s_U[NB][NB + 1];
        float s_abs[NB];
        int   s_src[N];
        int   s_na;
    } p;
    struct {
        float D[NB][NB + 1];
        float sL[128][NB + 1];
        float sU[NB][132];
    } r;
};

// panel role: registers-resident shift-array factorization (validated R6/R10
// math: same pivot policy, same FFMA order). No trailing swap here; the
// (dst,src) pairs are dumped for the swap kernels.
__device__ void panel_role(SmemU* sm, int k, int m) {
    float* A = g_lu + (size_t)m * NN;
    int kb = k * NB;
    int R  = N - kb;
    int tid = threadIdx.x;
    int lane = tid & 31, wrp = tid >> 5;

    int relA = tid, relB = tid + 512;
    bool actA = relA < R, actB = relB < R;
    int myA = relA, myB = relB;
    int exA = -1, exB = -1;

    float ca[NB], cb[NB];
    {
        const float4* pa = (const float4*)(A + (size_t)(kb + relA) * N + kb);
        const float4* pb = (const float4*)(A + (size_t)(kb + relB) * N + kb);
        #pragma unroll
        for (int q = 0; q < 8; q++) {
            float4 v = actA ? pa[q] : make_float4(0.f, 0.f, 0.f, 0.f);
            ca[4*q+0] = v.x; ca[4*q+1] = v.y; ca[4*q+2] = v.z; ca[4*q+3] = v.w;
            float4 w = actB ? pb[q] : make_float4(0.f, 0.f, 0.f, 0.f);
            cb[4*q+0] = w.x; cb[4*q+1] = w.y; cb[4*q+2] = w.z; cb[4*q+3] = w.w;
        }
    }
    if (tid == 0) sm->p.s_na = 0;

    #pragma unroll 1
    for (int j = 0; j < NB; j++) {
        unsigned long long key = 0ull;
        if (actA)
            key = ((unsigned long long)__float_as_uint(fabsf(ca[0])) << 32)
                | (unsigned long long)(0xFFFFFFFFu - (unsigned)myA);
        if (actB) {
            unsigned long long k2 =
                  ((unsigned long long)__float_as_uint(fabsf(cb[0])) << 32)
                | (unsigned long long)(0xFFFFFFFFu - (unsigned)myB);
            if (k2 > key) key = k2;
        }
        #pragma unroll
        for (int o = 16; o > 0; o >>= 1) {
            unsigned long long ok = __shfl_down_sync(0xffffffffu, key, o);
            if (ok > key) key = ok;
        }
        if (lane == 0) sm->p.rvi[wrp] = key;
        __syncthreads();

        unsigned long long bk = sm->p.rvi[0];
        #pragma unroll
        for (int w = 1; w < 16; w++) if (sm->p.rvi[w] > bk) bk = sm->p.rvi[w];
        int p = (int)(0xFFFFFFFFu - (unsigned)(bk & 0xFFFFFFFFull));
        if (tid == 0) sm->p.s_abs[j] = __uint_as_float((unsigned)(bk >> 32));

        if (actA) {
            if (myA == p) {
                #pragma unroll
                for (int t = 0; t < NB; t++) {
                    float v = ca[t];
                    int col = (t <= NB - 1 - j) ? (j + t) : (t - (NB - j));
                    sm->p.s_U[j][col] = v;
                    sm->p.s_piv[t] = (t <= NB - 1 - j) ? v : 0.0f;
                }
                actA = false; exA = j;
            } else if (myA == j) myA = p;
        }
        if (actB) {
            if (myB == p) {
                #pragma unroll
                for (int t = 0; t < NB; t++) {
                    float v = cb[t];
                    int col = (t <= NB - 1 - j) ? (j + t) : (t - (NB - j));
                    sm->p.s_U[j][col] = v;
                    sm->p.s_piv[t] = (t <= NB - 1 - j) ? v : 0.0f;
                }
                actB = false; exB = j;
            } else if (myB == j) myB = p;
        }
        __syncthreads();

        float inv = 1.0f / sm->p.s_piv[0];
        if (actA) {
            float lv = ca[0] * inv;
            #pragma unroll
            for (int t = 1; t < NB; t++) ca[t-1] = ca[t] - lv * sm->p.s_piv[t];
            ca[NB-1] = lv;
        }
        if (actB) {
            float lv = cb[0] * inv;
            #pragma unroll
            for (int t = 1; t < NB; t++) cb[t-1] = cb[t] - lv * sm->p.s_piv[t];
            cb[NB-1] = lv;
        }
    }
    __syncthreads();

    for (int i = tid; i < NB * NB; i += 512)
        A[(size_t)(kb + i / NB) * N + kb + (i % NB)] = sm->p.s_U[i / NB][i % NB];

    if (actA) {
        float4* pw = (float4*)(A + (size_t)(kb + myA) * N + kb);
        #pragma unroll
        for (int q = 0; q < 8; q++)
            pw[q] = make_float4(ca[4*q+0], ca[4*q+1], ca[4*q+2], ca[4*q+3]);
    }
    if (actB) {
        float4* pw = (float4*)(A + (size_t)(kb + myB) * N + kb);
        #pragma unroll
        for (int q = 0; q < 8; q++)
            pw[q] = make_float4(cb[4*q+0], cb[4*q+1], cb[4*q+2], cb[4*q+3]);
    }

    if (tid < 32) {
        float lg = logf(fmaxf(sm->p.s_abs[tid], 1e-45f));
        #pragma unroll
        for (int o = 16; o > 0; o >>= 1) lg += __shfl_down_sync(0xffffffffu, lg, o);
        if (tid == 0) g_logdet[m] += lg;
    }

    if (relA < R) {
        if (exA >= 0) sm->p.s_src[exA] = relA; else sm->p.s_src[myA] = relA;
    }
    if (relB < R) {
        if (exB >= 0) sm->p.s_src[exB] = relB; else sm->p.s_src[myB] = relB;
    }
    __syncthreads();
    for (int r = tid; r < R; r += 512) {
        if (sm->p.s_src[r] != r) {
            int i = atomicAdd(&sm->p.s_na, 1);
            g_aff[m * 64 + i] = r;
            g_srcof[m * 64 + i] = sm->p.s_src[r];
        }
    }
    __syncthreads();
    if (tid == 0) g_na[m] = sm->p.s_na;
}

// rest role: local-TRSM + trailing update on cols [kb+64, N), 128x128 tile,
// 512 threads, 4x8 per thread. Same math as validated lu_rest.
__device__ void rest_role(SmemU* sm, int k, int m, int t, int nx) {
    int kb   = k * NB;
    int off  = kb + NB;
    int coff = kb + 2 * NB;
    int Wr = N - off;
    int Wc = N - coff;
    float* A = g_lu + (size_t)m * NN;
    int r0 = (t / nx) * 128, c0 = (t % nx) * 128;
    int tid = threadIdx.x;

    for (int i = tid; i < NB * NB; i += 512) {
        int r = i / NB, c = i % NB;
        sm->r.D[r][c] = A[(size_t)(kb + r) * N + kb + c];
    }
    for (int i = tid; i < 128 * NB; i += 512) {
        int r = i / NB, j = i % NB;
        sm->r.sL[r][j] = (r0 + r < Wr) ? A[(size_t)(off + r0 + r) * N + kb + j] : 0.0f;
    }
    for (int i = tid; i < NB * 128; i += 512) {
        int r = i / 128, c = i % 128;
        int col = c0 + c;
        sm->r.sU[r][c] = (col < Wc) ? A[(size_t)(kb + r) * N + coff + col] : 0.0f;
    }
    __syncthreads();

    if (tid < 128) {
        float v[NB];
        #pragma unroll
        for (int i = 0; i < NB; i++) v[i] = sm->r.sU[i][tid];
        #pragma unroll 1
        for (int j = 0; j < NB; j++) {
            float vj = v[j];
            #pragma unroll
            for (int i = 0; i < NB; i++)
                if (i > j) v[i] -= sm->r.D[i][j] * vj;
        }
        #pragma unroll
        for (int i = 0; i < NB; i++) sm->r.sU[i][tid] = v[i];
    }
    __syncthreads();

    int tx = tid & 15, ty = tid >> 4;       // ty 0..31 -> 4-row groups
    float acc[4][8] = {};
    #pragma unroll
    for (int j = 0; j < NB; j++) {
        float4 b0 = *(const float4*)&sm->r.sU[j][tx * 4];
        float4 b1 = *(const float4*)&sm->r.sU[j][64 + tx * 4];
        float b[8] = {b0.x, b0.y, b0.z, b0.w, b1.x, b1.y, b1.z, b1.w};
        float a[4];
        #pragma unroll
        for (int i = 0; i < 4; i++) a[i] = sm->r.sL[ty * 4 + i][j];
        #pragma unroll
        for (int i = 0; i < 4; i++)
            #pragma unroll
            for (int l = 0; l < 8; l++) acc[i][l] += a[i] * b[l];
    }
    #pragma unroll
    for (int i = 0; i < 4; i++) {
        int row = r0 + ty * 4 + i;
        if (row >= Wr) continue;
        float* orow = A + (size_t)(off + row) * N + coff;
        #pragma unroll
        for (int l = 0; l < 8; l++) {
            int col = c0 + ((l < 4) ? (tx * 4 + l) : (64 + tx * 4 + l - 4));
            if (col < Wc) orow[col] -= acc[i][l];
        }
    }
}

__global__ void __launch_bounds__(512) fused_step(int kp, int kr, int nx) {
    __shared__ SmemU sm;
    if (blockIdx.y == 0) {
        panel_role(&sm, kp, blockIdx.x);
    } else if (kr >= 0) {
        rest_role(&sm, kr, blockIdx.x, blockIdx.y - 1, nx);
    }
}

// ---------------- swap kernels: permutation gather/scatter on trailing cols ----
__global__ void __launch_bounds__(256) swap_gather(int k) {
    int m = blockIdx.z, i = blockIdx.y;
    if (i >= g_na[m]) return;
    int kb = k * NB;
    int W  = N - kb - NB;
    int sr = g_srcof[m * 64 + i];
    const float4* src = (const float4*)(g_lu + (size_t)m * NN + (size_t)(kb + sr) * N + kb + NB);
    float4* dst = (float4*)(g_swaptmp + (size_t)m * 64 * N + (size_t)i * N);
    for (int c = threadIdx.x; c < (W >> 2); c += 256) dst[c] = src[c];
}

__global__ void __launch_bounds__(256) swap_scatter(int k) {
    int m = blockIdx.z, i = blockIdx.y;
    if (i >= g_na[m]) return;
    int kb = k * NB;
    int W  = N - kb - NB;
    int dr = g_aff[m * 64 + i];
    const float4* src = (const float4*)(g_swaptmp + (size_t)m * 64 * N + (size_t)i * N);
    float4* dst = (float4*)(g_lu + (size_t)m * NN + (size_t)(kb + dr) * N + kb + NB);
    for (int c = threadIdx.x; c < (W >> 2); c += 256) dst[c] = src[c];
}

// ---------------- narrow update: next panel's 32 columns, full rows ----------------
__global__ void __launch_bounds__(256) lu_narrow(int k) {
    int kb  = k * NB;
    int off = kb + NB;
    int W   = N - off;
    int m   = blockIdx.z;
    float* A = g_lu + (size_t)m * NN;
    int r0 = blockIdx.y * 128;
    int tid = threadIdx.x;

    __shared__ float D[NB][NB + 1];
    __shared__ float sL[128][NB + 1];
    __shared__ float sU[NB][NB + 4];

    for (int i = tid; i < NB * NB; i += 256) {
        int r = i / NB, c = i % NB;
        D[r][c] = A[(size_t)(kb + r) * N + kb + c];
    }
    for (int i = tid; i < 128 * NB; i += 256) {
        int r = i / NB, j = i % NB;
        sL[r][j] = (r0 + r < W) ? A[(size_t)(off + r0 + r) * N + kb + j] : 0.0f;
    }
    for (int i = tid; i < NB * NB; i += 256) {
        int r = i / NB, c = i % NB;
        sU[r][c] = A[(size_t)(kb + r) * N + off + c];
    }
    __syncthreads();

    if (tid < NB) {
        float v[NB];
        #pragma unroll
        for (int i = 0; i < NB; i++) v[i] = sU[i][tid];
        #pragma unroll 1
        for (int j = 0; j < NB; j++) {
            float vj = v[j];
            #pragma unroll
            for (int i = 0; i < NB; i++)
                if (i > j) v[i] -= D[i][j] * vj;
        }
        #pragma unroll
        for (int i = 0; i < NB; i++) sU[i][tid] = v[i];
    }
    __syncthreads();

    int tx = tid & 7, ty = tid >> 3;
    float acc[4][4] = {};
    #pragma unroll
    for (int j = 0; j < NB; j++) {
        float4 bv = *(const float4*)&sU[j][tx * 4];
        float b[4] = {bv.x, bv.y, bv.z, bv.w};
        float a[4];
        #pragma unroll
        for (int i = 0; i < 4; i++) a[i] = sL[ty * 4 + i][j];
        #pragma unroll
        for (int i = 0; i < 4; i++)
            #pragma unroll
            for (int l = 0; l < 4; l++) acc[i][l] += a[i] * b[l];
    }
    #pragma unroll
    for (int i = 0; i < 4; i++) {
        int row = r0 + ty * 4 + i;
        if (row >= W) continue;
        float* orow = A + (size_t)(off + row) * N + off;
        #pragma unroll
        for (int l = 0; l < 4; l++) orow[tx * 4 + l] -= acc[i][l];
    }
}

// ---------------- stage C: scores, top-k, fused weights, bool output ----------------
__global__ void head_kernel(const unsigned char* __restrict__ flags,
                            const float* __restrict__ w1, const float* __restrict__ b1,
                            const float* __restrict__ w2, const float* __restrict__ b2,
                            float* __restrict__ out, int out_size) {
    if (blockIdx.x != 0 || threadIdx.x != 0) return;

    int f[16];
    bool any_off4 = false;
    for (int i = 0; i < 16; i++)
        if ((i & 3) && flags[i]) any_off4 = true;
    if (any_off4) {
        for (int i = 0; i < 16; i++) f[i] = flags[i] ? 1 : 0;
    } else {
        const int* fi = (const int*)flags;
        for (int i = 0; i < 16; i++) f[i] = fi[i] ? 1 : 0;
    }

    int sum = 0;
    for (int i = 0; i < 16; i++) sum += f[i];
    int active = (sum >= 4) ? 1 : 0;

    float neg_inf = __int_as_float(0xff800000);
    float sc[16];
    for (int i = 0; i < 16; i++) sc[i] = f[i] ? g_logdet[i] : neg_inf;

    int used[16] = {};
    for (int t = 0; t < 8; t++) {
        int best = -1;
        float bv = neg_inf;
        for (int i = 0; i < 16; i++) {
            if (used[i]) continue;
            if (best < 0 || sc[i] > bv) { best = i; bv = sc[i]; }
        }
        used[best] = 1;
        g_hdr.idx[t] = best;
    }

    for (int c = 0; c < 10; c++) {
        float a = 0.0f;
        for (int h = 0; h < 32; h++) a += w2[h] * w1[h * 10 + c];
        g_hdr.weff[c] = a;
    }
    float be = b2[0];
    for (int h = 0; h < 32; h++) be += w2[h] * b1[h];
    g_hdr.beff = be;
    g_hdr.active = active;

    for (int i = NN; i < out_size; i++) out[i] = active ? 1.0f : 0.0f;
}

// ---------------- stage D1: combined right matrices ----------------
__global__ void combine_kernel(const float* __restrict__ x) {
    int i = blockIdx.x * blockDim.x + threadIdx.x;
    if (i >= NN / 4) return;
    const float4* T1 = (const float4*)(x + (size_t)g_hdr.idx[1] * NN);
    const float4* T2 = (const float4*)(x + (size_t)g_hdr.idx[2] * NN);
    const float4* T3 = (const float4*)(x + (size_t)g_hdr.idx[3] * NN);
    float w0 = g_hdr.weff[0], w1 = g_hdr.weff[1], w2 = g_hdr.weff[2];
    float w3 = g_hdr.weff[3], w4 = g_hdr.weff[4], w5 = g_hdr.weff[5];
    float4 a = T1[i], b = T2[i], c = T3[i];
    float4 r0, r1, r2;
    r0.x = w0*a.x + w1*b.x + w2*c.x;  r0.y = w0*a.y + w1*b.y + w2*c.y;
    r0.z = w0*a.z + w1*b.z + w2*c.z;  r0.w = w0*a.w + w1*b.w + w2*c.w;
    r1.x = w3*b.x + w4*c.x;  r1.y = w3*b.y + w4*c.y;
    r1.z = w3*b.z + w4*c.z;  r1.w = w3*b.w + w4*c.w;
    r2.x = w5*c.x;  r2.y = w5*c.y;  r2.z = w5*c.z;  r2.w = w5*c.w;
    ((float4*)g_comb)[i]            = r0;
    ((float4*)(g_comb + NN))[i]     = r1;
    ((float4*)(g_comb + 2*NN))[i]   = r2;
}

// ---------------- stage D2: fused 3-GEMM + preserve channels + bias ----------------
#define SA(p,r,j) sA[((p) * 128 + (r)) * 33 + (j)]
#define SB(p,j,c) sB[((p) * NB + (j)) * 68 + (c)]
__global__ void __launch_bounds__(256) final_kernel(const float* __restrict__ x,
                                                    float* __restrict__ out, int out_size) {
    extern __shared__ float sm[];
    float* sA = sm;                         // 3 * 128 * 33
    float* sB = sm + 3 * 128 * 33;          // 3 * NB * 68

    int r0 = blockIdx.y * 128, c0 = blockIdx.x * 64;
    int tid = threadIdx.x, tx = tid & 15, ty = tid >> 4;

    if (!g_hdr.active) {
        #pragma unroll
        for (int i = 0; i < 8; i++) {
            int row = r0 + ty * 8 + i;
            #pragma unroll
            for (int l = 0; l < 4; l++) {
                int p = row * N + c0 + tx * 4 + l;
                if (p < out_size) out[p] = 0.0f;
            }
        }
        return;
    }

    const float* L[3] = { x + (size_t)g_hdr.idx[0] * NN,
                          x + (size_t)g_hdr.idx[1] * NN,
                          x + (size_t)g_hdr.idx[2] * NN };
    const float* C[3] = { g_comb, g_comb + NN, g_comb + 2 * NN };

    float acc[8][4] = {};
    for (int kc = 0; kc < N; kc += NB) {
        #pragma unroll
        for (int p = 0; p < 3; p++) {
            for (int i = tid; i < 128 * NB; i += 256) {
                int r = i / NB, j = i % NB;
                SA(p, r, j) = L[p][(size_t)(r0 + r) * N + kc + j];
            }
            for (int i = tid; i < NB * 64; i += 256) {
                int j = i / 64, c = i % 64;
                SB(p, j, c) = C[p][(size_t)(kc + j) * N + c0 + c];
            }
        }
        __syncthreads();
        #pragma unroll 4
        for (int jj = 0; jj < NB; jj++) {
            #pragma unroll
            for (int p = 0; p < 3; p++) {
                float4 bv = *(const float4*)&SB(p, jj, tx * 4);
                float b[4] = {bv.x, bv.y, bv.z, bv.w};
                float a[8];
                #pragma unroll
                for (int i = 0; i < 8; i++) a[i] = SA(p, ty * 8 + i, jj);
                #pragma unroll
                for (int i = 0; i < 8; i++)
                    #pragma unroll
                    for (int l = 0; l < 4; l++) acc[i][l] += a[i] * b[l];
            }
        }
        __syncthreads();
    }

    const float* P0 = x + (size_t)g_hdr.idx[4] * NN;
    const float* P1 = x + (size_t)g_hdr.idx[5] * NN;
    const float* P2 = x + (size_t)g_hdr.idx[6] * NN;
    const float* P3 = x + (size_t)g_hdr.idx[7] * NN;
    float w6 = g_hdr.weff[6], w7 = g_hdr.weff[7], w8 = g_hdr.weff[8], w9 = g_hdr.weff[9];
    float be = g_hdr.beff;

    #pragma unroll
    for (int i = 0; i < 8; i++) {
        int row = r0 + ty * 8 + i;
        #pragma unroll
        for (int l = 0; l < 4; l++) {
            int col = c0 + tx * 4 + l;
            int p = row * N + col;
            float v = acc[i][l] + w6 * P0[p] + w7 * P1[p] + w8 * P2[p] + w9 * P3[p] + be;
            if (p < out_size) out[p] = v;
        }
    }
}

// ---------------- host launcher: single stream, in-launch overlap ----------------
extern "C" void kernel_launch(void* const* d_in, const int* in_sizes, int n_in,
                              void* d_out, int out_size) {
    const float*         x     = (const float*)d_in[0];
    const unsigned char* flags = (const unsigned char*)d_in[1];
    const float*         w1    = (const float*)d_in[2];
    const float*         b1    = (const float*)d_in[3];
    const float*         w2    = (const float*)d_in[4];
    const float*         b2    = (const float*)d_in[5];
    float*               out   = (float*)d_out;

    int fin_smem = (3 * 128 * 33 + 3 * NB * 68) * (int)sizeof(float);
    cudaFuncSetAttribute(final_kernel, cudaFuncAttributeMaxDynamicSharedMemorySize, fin_smem);

    copy_kernel<<<(BATCH * NN / 4 + 255) / 256, 256>>>(x);

    // initial panel (no rest work): grid (16, 1)
    fused_step<<<dim3(16, 1, 1), 512>>>(0, -1, 1);

    for (int k = 0; k < NSTEP - 1; k++) {
        swap_gather<<<dim3(1, 64, BATCH), 256>>>(k);
        swap_scatter<<<dim3(1, 64, BATCH), 256>>>(k);
        int Wr = N - (k + 1) * NB;
        lu_narrow<<<dim3(1, (Wr + 127) / 128, BATCH), 256>>>(k);

        int Wc = N - (k + 2) * NB;
        int nx = (Wc > 0) ? (Wc + 127) / 128 : 0;
        int ny = (Wr + 127) / 128;
        int ntiles = (Wc > 0) ? nx * ny : 0;
        // panel(k+1) CTAs (y==0, first in linear order) overlap rest(k) tiles
        fused_step<<<dim3(16, 1 + ntiles, 1), 512>>>(k + 1, (ntiles > 0) ? k : -1,
                                                     (nx > 0) ? nx : 1);
    }

    head_kernel<<<1, 1>>>(flags, w1, b1, w2, b2, out, out_size);
    combine_kernel<<<(NN / 4 + 255) / 256, 256>>>(x);
    final_kernel<<<dim3(16, 8), 256, fin_smem>>>(x, out, out_size);
}